// round 17
// baseline (speedup 1.0000x reference)
#include <cuda_runtime.h>
#include <cuda_bf16.h>
#include <cstdint>

// RaySampler: N=32 cameras, resolution=512 (M=262144 rays/cam).
// Output (fp32): [ray_origins (N,M,3)][ray_dirs (N,M,3)] = 201.3 MB writes.
//
// R16 lesson: fused-per-256-slot blocks paid the thread-0 prologue
// (LDG cam/intr + divides + syncthreads) 24576 times. This round: ONE wave of
// 1024 big blocks (256 thr, 24 coalesced float4 slots per thread, stride 256).
// Prologue runs once per block, all concurrently at t=0. Camera index is
// blockIdx.x>>5 (32 blocks per camera, exact). Slot decomposition q=l/3,p=l%3
// is computed once and advanced incrementally (+256 slots => q+=85, p+=1 w/
// wrap). Body per iteration: ~15 FMA, 2 rsqrt, selects, 1 LDS.128,
// 2 streaming STG.128.

static constexpr int RES = 512;
static constexpr int M_RAYS = RES * RES;                    // 262144
static constexpr int SLOTS_PER_CAM = M_RAYS * 3 / 4;        // 196608 float4s
static constexpr int ITERS = 24;
static constexpr int SLOTS_PER_BLOCK = 256 * ITERS;         // 6144
static constexpr int BLOCKS_PER_CAM = SLOTS_PER_CAM / SLOTS_PER_BLOCK; // 32
static constexpr float INV_RES = 1.0f / (float)RES;

__global__ void __launch_bounds__(256)
ray_sampler_kernel(const float* __restrict__ cam,     // (N,4,4)
                   const float* __restrict__ intr,    // (N,3,3)
                   float4* __restrict__ out_org,
                   float4* __restrict__ out_dir)
{
    __shared__ float4 sT[3];    // [0]=P [1]=Q [2]=R (w unused)
    __shared__ float4 sOV[3];   // origin float4 pattern for p=0,1,2

    const int n = (int)(blockIdx.x >> 5);                  // camera, block-uniform

    if (threadIdx.x == 0) {
        const float* Mn = cam + n * 16;
        const float3 A = make_float3(Mn[0], Mn[4], Mn[8]);     // rot col 0
        const float3 B = make_float3(Mn[1], Mn[5], Mn[9]);     // rot col 1
        const float3 C = make_float3(-Mn[2], -Mn[6], -Mn[10]); // -rot col 2
        const float ox = Mn[3], oy = Mn[7], oz = Mn[11];

        const float* In = intr + n * 9;
        const float fx = In[0], sk = In[1], cx = In[2];
        const float fy = In[4], cy = In[5];
        const float ifx = 1.0f / fx;
        const float ify = 1.0f / fy;

        // Unnormalized dir is affine in pixel: w = P*col + Q*row + R.
        const float s  = sk * ify * ifx;
        const float rx = (cy * sk * ify - cx) * ifx;
        const float ry = cy * ify;

        float3 P, Q, R;
        P.x = A.x * ifx;                 P.y = A.y * ifx;                 P.z = A.z * ifx;
        Q.x = -(A.x * s + B.x * ify);    Q.y = -(A.y * s + B.y * ify);    Q.z = -(A.z * s + B.z * ify);
        R.x = A.x * rx + B.x * ry + C.x; R.y = A.y * rx + B.y * ry + C.y; R.z = A.z * rx + B.z * ry + C.z;

        // Fold pixel scaling x_cam=(col+0.5)/RES, y_cam=(row+0.5)/RES.
        float3 Pp = make_float3(P.x * INV_RES, P.y * INV_RES, P.z * INV_RES);
        float3 Qp = make_float3(Q.x * INV_RES, Q.y * INV_RES, Q.z * INV_RES);
        float3 Rp = make_float3(R.x + 0.5f * (Pp.x + Qp.x),
                                R.y + 0.5f * (Pp.y + Qp.y),
                                R.z + 0.5f * (Pp.z + Qp.z));

        sT[0] = make_float4(Pp.x, Pp.y, Pp.z, 0.f);
        sT[1] = make_float4(Qp.x, Qp.y, Qp.z, 0.f);
        sT[2] = make_float4(Rp.x, Rp.y, Rp.z, 0.f);
        sOV[0] = make_float4(ox, oy, oz, ox);
        sOV[1] = make_float4(oy, oz, ox, oy);
        sOV[2] = make_float4(oz, ox, oy, oz);
    }
    __syncthreads();

    const float4 Pv = sT[0];
    const float4 Qv = sT[1];
    const float4 Rv = sT[2];

    // First slot for this thread; decompose once, then advance incrementally.
    unsigned l = blockIdx.x * (unsigned)SLOTS_PER_BLOCK + threadIdx.x;
    unsigned q = l / 3u;            // global ray quad
    int      p = (int)(l - q * 3u); // window phase

#pragma unroll 6
    for (int it = 0; it < ITERS; ++it) {
        const float rowf = (float)((q >> 7) & 511u);
        const float colf = (float)(((q & 127u) << 2) + (unsigned)p);  // ray A col

        // base = Q*row + R (shared by rays A and B)
        const float bx = fmaf(Qv.x, rowf, Rv.x);
        const float by = fmaf(Qv.y, rowf, Rv.y);
        const float bz = fmaf(Qv.z, rowf, Rv.z);

        // ray A (col), ray B (col+1) = A + P
        float ax = fmaf(Pv.x, colf, bx);
        float ay = fmaf(Pv.y, colf, by);
        float az = fmaf(Pv.z, colf, bz);
        float ex = ax + Pv.x;
        float ey = ay + Pv.y;
        float ez = az + Pv.z;

        const float ia = rsqrtf(fmaxf(fmaf(ax, ax, fmaf(ay, ay, az * az)), 1e-24f));
        const float ib = rsqrtf(fmaxf(fmaf(ex, ex, fmaf(ey, ey, ez * ez)), 1e-24f));
        ax *= ia; ay *= ia; az *= ia;
        ex *= ib; ey *= ib; ez *= ib;

        float4 dv;
        if (p == 0)      dv = make_float4(ax, ay, az, ex);
        else if (p == 1) dv = make_float4(ay, az, ex, ey);
        else             dv = make_float4(az, ex, ey, ez);

        __stcs(&out_dir[l], dv);       // coalesced streaming stores
        __stcs(&out_org[l], sOV[p]);

        // Advance 256 slots: 256 = 3*85 + 1.
        l += 256u;
        q += 85u;
        if (++p == 3) { p = 0; ++q; }
    }
}

extern "C" void kernel_launch(void* const* d_in, const int* in_sizes, int n_in,
                              void* d_out, int out_size)
{
    const float* cam  = (const float*)d_in[0];   // (N,4,4) fp32
    const float* intr = (const float*)d_in[1];   // (N,3,3) fp32
    const int N = in_sizes[0] / 16;              // 32

    const size_t T4 = (size_t)N * SLOTS_PER_CAM; // 6,291,456 float4s
    float4* out_org = (float4*)d_out;
    float4* out_dir = (float4*)d_out + T4;

    dim3 block(256);
    dim3 grid((unsigned)(N * BLOCKS_PER_CAM));   // 1024 blocks: one wave
    ray_sampler_kernel<<<grid, block>>>(cam, intr, out_org, out_dir);
}